// round 7
// baseline (speedup 1.0000x reference)
#include <cuda_runtime.h>
#include <cuda_bf16.h>

// Problem constants (from reference): P=8, N=16, WS=32, H=W=512.
#define PP     8
#define NSLOT  16
#define WSZ    32
#define PITCH  36            // row pitch (multiple of 4 for float4 alignment)
#define HDIM   512
#define WDIM   512
#define MAXM   625           // (32-8+1)^2
#define KPL    20            // elems per lane in selection warp (32*20=640>=625)

#define FINF __int_as_float(0x7f800000)

__global__ __launch_bounds__(256, 1)
void patches_kernel(const float* __restrict__ g_re,
                    const float* __restrict__ g_im,
                    const int*   __restrict__ p_refx,
                    const int*   __restrict__ p_refy,
                    float*       __restrict__ out)
{
    __shared__ float wr[WSZ][PITCH];
    __shared__ float wi[WSZ][PITCH];
    __shared__ float ref_r[PP * PP];
    __shared__ float ref_i[PP * PP];
    __shared__ float dists[MAXM];
    __shared__ unsigned s_mm[32 * KPL];   // per-element pile-membership masks
    __shared__ int   sel[NSLOT];

    const int bc   = blockIdx.x;
    const int tid  = threadIdx.x;
    const int lane = tid & 31;
    const int wrp  = tid >> 5;

    const int ref_x = *p_refx;
    const int ref_y = *p_refy;

    int wx0 = ref_x - WSZ / 2; if (wx0 < 0) wx0 = 0;
    int wx1 = ref_x + WSZ / 2; if (wx1 > HDIM) wx1 = HDIM;
    int wy0 = ref_y - WSZ / 2; if (wy0 < 0) wy0 = 0;
    int wy1 = ref_y + WSZ / 2; if (wy1 > WDIM) wy1 = WDIM;

    const int Wh = wx1 - wx0;
    const int Ww = wy1 - wy0;
    const int Ph = Wh - PP + 1;
    const int Pw = Ww - PP + 1;
    const int M  = Ph * Pw;

    const size_t base = (size_t)bc * HDIM * WDIM;

    // ---- Stage window into SMEM ----
    if (((wy0 & 3) == 0) && ((Ww & 3) == 0)) {
        const int nv = (Wh * Ww) >> 2;            // float4 count
        const int wv = Ww >> 2;
        for (int t = tid; t < nv; t += 256) {
            const int r  = t / wv;
            const int c4 = (t - r * wv) << 2;
            const size_t gidx = base + (size_t)(wx0 + r) * WDIM + (wy0 + c4);
            *(float4*)&wr[r][c4] = *(const float4*)&g_re[gidx];
            *(float4*)&wi[r][c4] = *(const float4*)&g_im[gidx];
        }
    } else {
        for (int t = tid; t < Wh * Ww; t += 256) {
            const int r = t / Ww;
            const int c = t - r * Ww;
            const size_t gidx = base + (size_t)(wx0 + r) * WDIM + (wy0 + c);
            wr[r][c] = g_re[gidx];
            wi[r][c] = g_im[gidx];
        }
    }
    if (tid < PP * PP) {
        const int i = tid >> 3, j = tid & 7;
        const size_t gidx = base + (size_t)(ref_x + i) * WDIM + (ref_y + j);
        ref_r[tid] = g_re[gidx];
        ref_i[tid] = g_im[gidx];
    }
    __syncthreads();

    // ---- Distances: i-outer / patch-inner so ref rows load once per thread.
    //      Per-patch accumulation order identical to reference (i, j, re, im).
    {
        const int mA = tid, mB = tid + 256, mC = tid + 512;
        const bool vB = (mB < M), vC = (mC < M);
        const int pxA = mA / Pw, pyA = mA - pxA * Pw;
        const int pxB = vB ? (mB / Pw) : 0;  const int pyB = vB ? (mB - pxB * Pw) : 0;
        const int pxC = vC ? (mC / Pw) : 0;  const int pyC = vC ? (mC - pxC * Pw) : 0;
        float sA = 0.0f, sB = 0.0f, sC = 0.0f;
        #pragma unroll
        for (int i = 0; i < PP; i++) {
            const float4 r0 = *(const float4*)&ref_r[i * PP + 0];
            const float4 r1 = *(const float4*)&ref_r[i * PP + 4];
            const float4 q0 = *(const float4*)&ref_i[i * PP + 0];
            const float4 q1 = *(const float4*)&ref_i[i * PP + 4];
            const float rrow[8] = {r0.x, r0.y, r0.z, r0.w, r1.x, r1.y, r1.z, r1.w};
            const float irow[8] = {q0.x, q0.y, q0.z, q0.w, q1.x, q1.y, q1.z, q1.w};
            {
                const float* ar = &wr[pxA + i][pyA];
                const float* ai = &wi[pxA + i][pyA];
                #pragma unroll
                for (int j = 0; j < PP; j++) {
                    const float dr = ar[j] - rrow[j];
                    const float dm = ai[j] - irow[j];
                    sA += dr * dr;  sA += dm * dm;
                }
            }
            if (vB) {
                const float* br = &wr[pxB + i][pyB];
                const float* bi = &wi[pxB + i][pyB];
                #pragma unroll
                for (int j = 0; j < PP; j++) {
                    const float dr = br[j] - rrow[j];
                    const float dm = bi[j] - irow[j];
                    sB += dr * dr;  sB += dm * dm;
                }
            }
            if (vC) {
                const float* cr = &wr[pxC + i][pyC];
                const float* ci = &wi[pxC + i][pyC];
                #pragma unroll
                for (int j = 0; j < PP; j++) {
                    const float dr = cr[j] - rrow[j];
                    const float dm = ci[j] - irow[j];
                    sC += dr * dr;  sC += dm * dm;
                }
            }
        }
        if (mA < M) dists[mA] = sA * (1.0f / 256.0f);
        if (vB)     dists[mB] = sB * (1.0f / 256.0f);
        if (vC)     dists[mC] = sC * (1.0f / 256.0f);
    }
    __syncthreads();

    // ---- Selection: 16 patience-sort rounds entirely inside warp 0.
    //      Pile-j members = strict prefix-minima of remaining subsequence.
    //      Membership recorded as bitmask; winners (max index) extracted later.
    if (tid < 32) {
        float    v[KPL];
        unsigned mm[KPL];
        #pragma unroll
        for (int k = 0; k < KPL; k++) {
            const int m = lane * KPL + k;
            v[k]  = (m < M) ? dists[m] : FINF;
            mm[k] = 0u;
        }
        for (int j = 0; j < NSLOT; j++) {
            float pmk[KPL];
            float rm = FINF;
            #pragma unroll
            for (int k = 0; k < KPL; k++) { pmk[k] = rm; rm = fminf(rm, v[k]); }
            float inc = rm;
            #pragma unroll
            for (int off = 1; off < 32; off <<= 1) {
                const float o = __shfl_up_sync(0xffffffffu, inc, off);
                if (lane >= off) inc = fminf(inc, o);
            }
            float bmin = __shfl_up_sync(0xffffffffu, inc, 1);
            if (lane == 0) bmin = FINF;
            const unsigned bit = 1u << j;
            #pragma unroll
            for (int k = 0; k < KPL; k++) {
                const float lim = fminf(bmin, pmk[k]);
                if (v[k] < lim) { mm[k] |= bit; v[k] = FINF; }
            }
        }
        #pragma unroll
        for (int k = 0; k < KPL; k++) s_mm[lane * KPL + k] = mm[k];
    }
    __syncthreads();

    // ---- Winner extraction: warp w finds max-index member of piles w, w+8.
    {
        const int s0 = wrp, s1 = wrp + 8;
        int win0 = -1, win1 = -1;
        #pragma unroll
        for (int i = 0; i < KPL; i++) {
            const unsigned msk = s_mm[i * 32 + lane];
            const unsigned b0 = __ballot_sync(0xffffffffu, (msk >> s0) & 1u);
            const unsigned b1 = __ballot_sync(0xffffffffu, (msk >> s1) & 1u);
            if (b0) win0 = i * 32 + (31 - __clz(b0));
            if (b1) win1 = i * 32 + (31 - __clz(b1));
        }
        if (lane == 0) { sel[s0] = win0; sel[s1] = win1; }
    }
    __syncthreads();

    // ---- Gather winning patches, 2048 coalesced floats per CTA.
    for (int t = tid; t < NSLOT * PP * PP * 2; t += 256) {
        const int comp = t & 1;
        const int k    = (t >> 1) & (PP * PP - 1);
        const int s    = t >> 7;
        const int m    = sel[s];
        float v = 0.0f;  // unfilled slot -> zeros (matches reference init)
        if (m >= 0) {
            const int px = m / Pw;
            const int py = m - px * Pw;
            const int i  = k >> 3;
            const int jj = k & 7;
            v = comp ? wi[px + i][py + jj] : wr[px + i][py + jj];
        }
        out[(size_t)bc * (NSLOT * PP * PP * 2) + t] = v;
    }
}

extern "C" void kernel_launch(void* const* d_in, const int* in_sizes, int n_in,
                              void* d_out, int out_size)
{
    const float* g_re = (const float*)d_in[0];
    const float* g_im = (const float*)d_in[1];
    const int*   refx = (const int*)d_in[2];
    const int*   refy = (const int*)d_in[3];
    float*       out  = (float*)d_out;

    const int BC = in_sizes[0] / (HDIM * WDIM);   // 96
    patches_kernel<<<BC, 256>>>(g_re, g_im, refx, refy, out);
}

// round 8
// speedup vs baseline: 1.1800x; 1.1800x over previous
#include <cuda_runtime.h>
#include <cuda_bf16.h>

// Problem constants (from reference): P=8, N=16, WS=32, H=W=512.
#define PP     8
#define NSLOT  16
#define WSZ    32
#define PITCH2 34            // window row pitch in float2 units (16B-aligned rows)
#define HDIM   512
#define WDIM   512
#define MAXM   625           // (32-8+1)^2
#define KPL    20            // elems per lane in selection warp (32*20=640>=625)

#define FINF __int_as_float(0x7f800000)

typedef unsigned long long u64;

__device__ __forceinline__ u64 pack2(float lo, float hi) {
    u64 r;
    asm("mov.b64 %0, {%1, %2};" : "=l"(r) : "f"(lo), "f"(hi));
    return r;
}
__device__ __forceinline__ float2 unpack2(u64 v) {
    float2 f;
    asm("mov.b64 {%0, %1}, %2;" : "=f"(f.x), "=f"(f.y) : "l"(v));
    return f;
}
// Packed fp32 add: (a.lo+b.lo, a.hi+b.hi), round-to-nearest, bit-identical
// to the two scalar adds.
__device__ __forceinline__ u64 add2(u64 a, u64 b) {
    u64 r;
    asm("add.rn.f32x2 %0, %1, %2;" : "=l"(r) : "l"(a), "l"(b));
    return r;
}

__global__ __launch_bounds__(256, 1)
void patches_kernel(const float* __restrict__ g_re,
                    const float* __restrict__ g_im,
                    const int*   __restrict__ p_refx,
                    const int*   __restrict__ p_refy,
                    float*       __restrict__ out)
{
    __shared__ u64   wp[WSZ][PITCH2];      // interleaved (re, im) window
    __shared__ u64   nref[PP][PP];         // NEGATED ref patch, interleaved
    __shared__ float dists[MAXM];
    __shared__ unsigned s_mm[32 * KPL];    // per-element pile-membership masks
    __shared__ int   sel[NSLOT];

    const int bc   = blockIdx.x;
    const int tid  = threadIdx.x;
    const int lane = tid & 31;
    const int wrp  = tid >> 5;

    const int ref_x = *p_refx;
    const int ref_y = *p_refy;

    int wx0 = ref_x - WSZ / 2; if (wx0 < 0) wx0 = 0;
    int wx1 = ref_x + WSZ / 2; if (wx1 > HDIM) wx1 = HDIM;
    int wy0 = ref_y - WSZ / 2; if (wy0 < 0) wy0 = 0;
    int wy1 = ref_y + WSZ / 2; if (wy1 > WDIM) wy1 = WDIM;

    const int Wh = wx1 - wx0;
    const int Ww = wy1 - wy0;
    const int Ph = Wh - PP + 1;
    const int Pw = Ww - PP + 1;
    const int M  = Ph * Pw;

    const size_t base = (size_t)bc * HDIM * WDIM;

    // ---- Stage window into SMEM, interleaved ----
    if (((wy0 & 3) == 0) && ((Ww & 3) == 0)) {
        const int nv = (Wh * Ww) >> 2;            // float4 count per array
        const int wv = Ww >> 2;
        for (int t = tid; t < nv; t += 256) {
            const int r  = t / wv;
            const int c4 = (t - r * wv) << 2;
            const size_t gidx = base + (size_t)(wx0 + r) * WDIM + (wy0 + c4);
            const float4 re = *(const float4*)&g_re[gidx];
            const float4 im = *(const float4*)&g_im[gidx];
            wp[r][c4 + 0] = pack2(re.x, im.x);
            wp[r][c4 + 1] = pack2(re.y, im.y);
            wp[r][c4 + 2] = pack2(re.z, im.z);
            wp[r][c4 + 3] = pack2(re.w, im.w);
        }
    } else {
        for (int t = tid; t < Wh * Ww; t += 256) {
            const int r = t / Ww;
            const int c = t - r * Ww;
            const size_t gidx = base + (size_t)(wx0 + r) * WDIM + (wy0 + c);
            wp[r][c] = pack2(g_re[gidx], g_im[gidx]);
        }
    }
    // Negated ref patch (negation is exact; w + (-r) == w - r bitwise).
    if (tid < PP * PP) {
        const int i = tid >> 3, j = tid & 7;
        const size_t gidx = base + (size_t)(ref_x + i) * WDIM + (ref_y + j);
        nref[i][j] = pack2(-g_re[gidx], -g_im[gidx]);
    }
    __syncthreads();

    // ---- Distances. Accumulation per patch identical to reference:
    //      i ascending, j ascending, re then im, single accumulator.
    if (Ph == (WSZ - PP + 1) && Pw == (WSZ - PP + 1)) {
        // Fast path: 125 threads, each a horizontal group of 5 patches
        // sharing row loads (12 pairs serve 5 patches).
        if (tid < 125) {
            const int px  = tid / 5;
            const int py0 = (tid - px * 5) * 5;
            float s0 = 0.f, s1 = 0.f, s2 = 0.f, s3 = 0.f, s4 = 0.f;
            #pragma unroll
            for (int i = 0; i < PP; i++) {
                u64 nr[PP];
                #pragma unroll
                for (int j = 0; j < PP; j += 2) {
                    const ulonglong2 q = *(const ulonglong2*)&nref[i][j];
                    nr[j] = q.x; nr[j + 1] = q.y;
                }
                u64 w[12];
                #pragma unroll
                for (int c = 0; c < 12; c++) w[c] = wp[px + i][py0 + c];
                #pragma unroll
                for (int p = 0; p < 5; p++) {
                    float* sp = (p == 0) ? &s0 : (p == 1) ? &s1 : (p == 2) ? &s2
                              : (p == 3) ? &s3 : &s4;
                    float s = *sp;
                    #pragma unroll
                    for (int j = 0; j < PP; j++) {
                        const float2 d = unpack2(add2(w[p + j], nr[j]));
                        s = fmaf(d.x, d.x, s);
                        s = fmaf(d.y, d.y, s);
                    }
                    *sp = s;
                }
            }
            const int mb = px * Pw + py0;
            dists[mb + 0] = s0 * (1.0f / 256.0f);
            dists[mb + 1] = s1 * (1.0f / 256.0f);
            dists[mb + 2] = s2 * (1.0f / 256.0f);
            dists[mb + 3] = s3 * (1.0f / 256.0f);
            dists[mb + 4] = s4 * (1.0f / 256.0f);
        }
    } else {
        // Generic fallback (any window shape).
        for (int m = tid; m < M; m += 256) {
            const int px = m / Pw;
            const int py = m - px * Pw;
            float s = 0.0f;
            #pragma unroll
            for (int i = 0; i < PP; i++) {
                #pragma unroll
                for (int j = 0; j < PP; j++) {
                    const float2 d = unpack2(add2(wp[px + i][py + j], nref[i][j]));
                    s = fmaf(d.x, d.x, s);
                    s = fmaf(d.y, d.y, s);
                }
            }
            dists[m] = s * (1.0f / 256.0f);
        }
    }
    __syncthreads();

    // ---- Selection: 16 patience-sort rounds in warp 0 (exact replay of
    //      reference slot semantics). Pile-j members = strict prefix-minima
    //      of the remaining subsequence; slot j = last member.
    if (tid < 32) {
        float    v[KPL];
        unsigned mm[KPL];
        #pragma unroll
        for (int k = 0; k < KPL; k++) {
            const int m = lane * KPL + k;
            v[k]  = (m < M) ? dists[m] : FINF;
            mm[k] = 0u;
        }
        for (int j = 0; j < NSLOT; j++) {
            // Tree-min (short dep chain) feeds the scan immediately.
            float t[KPL];
            #pragma unroll
            for (int k = 0; k < KPL; k++) t[k] = v[k];
            #pragma unroll
            for (int h = 10; h > 0; h >>= 1) {   // 20 -> 10 -> 5 -> (ceil) ...
                #pragma unroll
                for (int k = 0; k < KPL; k++)
                    if (k < h && k + h < ((h == 10) ? KPL : 2 * h))
                        t[k] = fminf(t[k], t[k + h]);
            }
            float tm5 = fminf(fminf(t[0], t[1]), fminf(fminf(t[2], t[3]), t[4]));
            float inc = tm5;
            #pragma unroll
            for (int off = 1; off < 32; off <<= 1) {
                const float o = __shfl_up_sync(0xffffffffu, inc, off);
                if (lane >= off) inc = fminf(inc, o);
            }
            float bmin = __shfl_up_sync(0xffffffffu, inc, 1);
            if (lane == 0) bmin = FINF;
            // Serial prefix-min (overlaps the shfl chain above in schedule).
            float pmk[KPL];
            float rm = FINF;
            #pragma unroll
            for (int k = 0; k < KPL; k++) { pmk[k] = rm; rm = fminf(rm, v[k]); }
            const unsigned bit = 1u << j;
            #pragma unroll
            for (int k = 0; k < KPL; k++) {
                const float lim = fminf(bmin, pmk[k]);
                if (v[k] < lim) { mm[k] |= bit; v[k] = FINF; }
            }
        }
        #pragma unroll
        for (int k = 0; k < KPL; k++) s_mm[lane * KPL + k] = mm[k];
    }
    __syncthreads();

    // ---- Winner extraction: warp w finds max-index member of piles w, w+8.
    {
        const int s0 = wrp, s1 = wrp + 8;
        int win0 = -1, win1 = -1;
        #pragma unroll
        for (int i = 0; i < KPL; i++) {
            const unsigned msk = s_mm[i * 32 + lane];
            const unsigned b0 = __ballot_sync(0xffffffffu, (msk >> s0) & 1u);
            const unsigned b1 = __ballot_sync(0xffffffffu, (msk >> s1) & 1u);
            if (b0) win0 = i * 32 + (31 - __clz(b0));
            if (b1) win1 = i * 32 + (31 - __clz(b1));
        }
        if (lane == 0) { sel[s0] = win0; sel[s1] = win1; }
    }
    __syncthreads();

    // ---- Gather winning patches: 1024 float2 stores per CTA.
    // out layout: [bc][slot][k=i*8+j][comp], comp fastest -> one float2 each.
    for (int t2 = tid; t2 < NSLOT * PP * PP; t2 += 256) {
        const int s = t2 >> 6;
        const int k = t2 & 63;
        const int m = sel[s];
        float2 v = make_float2(0.0f, 0.0f);   // unfilled slot -> zeros
        if (m >= 0) {
            const int px = m / Pw;
            const int py = m - px * Pw;
            v = unpack2(wp[px + (k >> 3)][py + (k & 7)]);
        }
        *(float2*)&out[(size_t)bc * (NSLOT * PP * PP * 2) + 2 * t2] = v;
    }
}

extern "C" void kernel_launch(void* const* d_in, const int* in_sizes, int n_in,
                              void* d_out, int out_size)
{
    const float* g_re = (const float*)d_in[0];
    const float* g_im = (const float*)d_in[1];
    const int*   refx = (const int*)d_in[2];
    const int*   refy = (const int*)d_in[3];
    float*       out  = (float*)d_out;

    const int BC = in_sizes[0] / (HDIM * WDIM);   // 96
    patches_kernel<<<BC, 256>>>(g_re, g_im, refx, refy, out);
}